// round 9
// baseline (speedup 1.0000x reference)
#include <cuda_runtime.h>

// Integrate-and-fire scan, TBN layout, pure HBM-streaming problem.
//   m_t = v_{t-1} + x_t ;  y_t = (m_t >= 1) ;  v_t = m_t - y_t
//
// R8: widen the confirmed write-burst mechanism to 8. Loads remain strictly
// paired (max 2 outstanding; >2 regressed in R2/R5 via cross-CTA L1tex queue
// contention). Stores: 8 consecutive STG.128 per warp = 8KB contiguous write
// bursts -> fewer DRAM read<->write turnarounds.
// Burst-width curve so far: 1-wide 78.3% DRAM, 2-wide 80.0%, 4-wide 81.7%.

#define T_STEPS 32

__device__ __forceinline__ void if_step(float4& v, float4 m, float4& s)
{
    m.x += v.x; m.y += v.y; m.z += v.z; m.w += v.w;
    s.x = (m.x >= 1.0f) ? 1.0f : 0.0f;
    s.y = (m.y >= 1.0f) ? 1.0f : 0.0f;
    s.z = (m.z >= 1.0f) ? 1.0f : 0.0f;
    s.w = (m.w >= 1.0f) ? 1.0f : 0.0f;
    v.x = m.x - s.x; v.y = m.y - s.y; v.z = m.z - s.z; v.w = m.w - s.w;
}

__global__ void __launch_bounds__(256) if_scan_kernel(
    const float4* __restrict__ x, float4* __restrict__ y, int bn4)
{
    const unsigned i = blockIdx.x * blockDim.x + threadIdx.x;

    const float4* xp = x + i;
    float4*       yp = y + i;

    float4 v = make_float4(0.f, 0.f, 0.f, 0.f);

    #pragma unroll
    for (int t = 0; t < T_STEPS; t += 8) {
        float4 s0, s1, s2, s3, s4, s5, s6, s7;

        {   // pair 1
            float4 a = xp[(unsigned)(t + 0) * (unsigned)bn4];
            float4 b = xp[(unsigned)(t + 1) * (unsigned)bn4];
            if_step(v, a, s0);
            if_step(v, b, s1);
        }
        {   // pair 2
            float4 a = xp[(unsigned)(t + 2) * (unsigned)bn4];
            float4 b = xp[(unsigned)(t + 3) * (unsigned)bn4];
            if_step(v, a, s2);
            if_step(v, b, s3);
        }
        {   // pair 3
            float4 a = xp[(unsigned)(t + 4) * (unsigned)bn4];
            float4 b = xp[(unsigned)(t + 5) * (unsigned)bn4];
            if_step(v, a, s4);
            if_step(v, b, s5);
        }
        {   // pair 4
            float4 a = xp[(unsigned)(t + 6) * (unsigned)bn4];
            float4 b = xp[(unsigned)(t + 7) * (unsigned)bn4];
            if_step(v, a, s6);
            if_step(v, b, s7);
        }

        // 8 stores back-to-back: 8KB contiguous write burst per warp
        yp[(unsigned)(t + 0) * (unsigned)bn4] = s0;
        yp[(unsigned)(t + 1) * (unsigned)bn4] = s1;
        yp[(unsigned)(t + 2) * (unsigned)bn4] = s2;
        yp[(unsigned)(t + 3) * (unsigned)bn4] = s3;
        yp[(unsigned)(t + 4) * (unsigned)bn4] = s4;
        yp[(unsigned)(t + 5) * (unsigned)bn4] = s5;
        yp[(unsigned)(t + 6) * (unsigned)bn4] = s6;
        yp[(unsigned)(t + 7) * (unsigned)bn4] = s7;
    }
}

extern "C" void kernel_launch(void* const* d_in, const int* in_sizes, int n_in,
                              void* d_out, int out_size)
{
    const float4* x = (const float4*)d_in[0];
    float4* y = (float4*)d_out;

    int total = in_sizes[0];           // T*B*N
    int bn = total / T_STEPS;          // B*N columns
    int bn4 = bn / 4;                  // 524288 float4 groups

    int threads = 256;
    int blocks = bn4 / threads;        // 2048, exact, no tail
    if_scan_kernel<<<blocks, threads>>>(x, y, bn4);
}

// round 10
// speedup vs baseline: 1.0522x; 1.0522x over previous
#include <cuda_runtime.h>

// Integrate-and-fire scan, TBN layout, pure HBM-streaming problem.
//   m_t = v_{t-1} + x_t ;  y_t = (m_t >= 1) ;  v_t = m_t - y_t
//
// R9: retry 8-wide store bursts WITH an explicit register budget.
// R8's regression was compiler-induced: ptxas picked 36 regs and spilled the
// 8 live s-values to local (L1 39.6->63.4%, fma/alu doubled). launch_bounds
// (256, 4) opens a 64-reg ceiling -> no spill. Loads stay strictly paired
// (max 2 outstanding; >2 regressed in R2/R5). 8 consecutive STG.128 per warp
// = 8KB contiguous write bursts.
// Burst curve (spill-free): 1-wide 78.3% DRAM, 2-wide 80.0%, 4-wide 81.7%.

#define T_STEPS 32

__device__ __forceinline__ void if_step(float4& v, float4 m, float4& s)
{
    m.x += v.x; m.y += v.y; m.z += v.z; m.w += v.w;
    s.x = (m.x >= 1.0f) ? 1.0f : 0.0f;
    s.y = (m.y >= 1.0f) ? 1.0f : 0.0f;
    s.z = (m.z >= 1.0f) ? 1.0f : 0.0f;
    s.w = (m.w >= 1.0f) ? 1.0f : 0.0f;
    v.x = m.x - s.x; v.y = m.y - s.y; v.z = m.z - s.z; v.w = m.w - s.w;
}

__global__ void __launch_bounds__(256, 4) if_scan_kernel(
    const float4* __restrict__ x, float4* __restrict__ y, int bn4)
{
    const unsigned i = blockIdx.x * blockDim.x + threadIdx.x;

    const float4* xp = x + i;
    float4*       yp = y + i;

    float4 v = make_float4(0.f, 0.f, 0.f, 0.f);

    #pragma unroll
    for (int t = 0; t < T_STEPS; t += 8) {
        float4 s0, s1, s2, s3, s4, s5, s6, s7;

        {   // pair 1
            float4 a = xp[(unsigned)(t + 0) * (unsigned)bn4];
            float4 b = xp[(unsigned)(t + 1) * (unsigned)bn4];
            if_step(v, a, s0);
            if_step(v, b, s1);
        }
        {   // pair 2
            float4 a = xp[(unsigned)(t + 2) * (unsigned)bn4];
            float4 b = xp[(unsigned)(t + 3) * (unsigned)bn4];
            if_step(v, a, s2);
            if_step(v, b, s3);
        }
        {   // pair 3
            float4 a = xp[(unsigned)(t + 4) * (unsigned)bn4];
            float4 b = xp[(unsigned)(t + 5) * (unsigned)bn4];
            if_step(v, a, s4);
            if_step(v, b, s5);
        }
        {   // pair 4
            float4 a = xp[(unsigned)(t + 6) * (unsigned)bn4];
            float4 b = xp[(unsigned)(t + 7) * (unsigned)bn4];
            if_step(v, a, s6);
            if_step(v, b, s7);
        }

        // 8 stores back-to-back: 8KB contiguous write burst per warp
        yp[(unsigned)(t + 0) * (unsigned)bn4] = s0;
        yp[(unsigned)(t + 1) * (unsigned)bn4] = s1;
        yp[(unsigned)(t + 2) * (unsigned)bn4] = s2;
        yp[(unsigned)(t + 3) * (unsigned)bn4] = s3;
        yp[(unsigned)(t + 4) * (unsigned)bn4] = s4;
        yp[(unsigned)(t + 5) * (unsigned)bn4] = s5;
        yp[(unsigned)(t + 6) * (unsigned)bn4] = s6;
        yp[(unsigned)(t + 7) * (unsigned)bn4] = s7;
    }
}

extern "C" void kernel_launch(void* const* d_in, const int* in_sizes, int n_in,
                              void* d_out, int out_size)
{
    const float4* x = (const float4*)d_in[0];
    float4* y = (float4*)d_out;

    int total = in_sizes[0];           // T*B*N
    int bn = total / T_STEPS;          // B*N columns
    int bn4 = bn / 4;                  // 524288 float4 groups

    int threads = 256;
    int blocks = bn4 / threads;        // 2048, exact, no tail
    if_scan_kernel<<<blocks, threads>>>(x, y, bn4);
}